// round 7
// baseline (speedup 1.0000x reference)
#include <cuda_runtime.h>
#include <cuda_bf16.h>

// WeaveLayer permutation:
//   out[b, yb*8 + hi*4 + px, xb*8 + wi*4 + py] = in[b, yb*4 + py, xb*4 + px, q=2*hi+wi]
// in (32, 768, 768, 4) f32, out (32, 1536, 1536, 1) f32.
//
// CTA = (b, yb): reads 4 full input rows (48 KB contiguous), writes 8 full output
// rows (48 KB contiguous). smem tile in OUTPUT layout, 8 rows x 1536 floats, with
// per-row XOR swizzle (16B granularity) so load-phase scalar STS is bank-conflict-free:
//   physical_c4 = c4 ^ f(px),  f(px) = px + ((px&2)<<1)  in {0,1,6,7}
// Lane map (load): py = tid&3, px = (tid>>2)&3, xb bit0 = tid bit4 -> each warp's
// LDG covers 4 full 128B lines (perfect coalescing) AND all 32 banks per STS.
//
// R6 change: streaming cache hints. Both streams are read-once / write-once over
// a 604 MB working set sweeping a 126 MB L2 — __ldcs / __stcs (evict-first) keep
// L2 from retaining dead lines and give the DRAM scheduler cleaner writeback
// bursts. Structure otherwise identical to the 92.7us kernel.

#define B_      32
#define YB      192           // 768 / 4
#define THREADS 512
#define ROWLEN  1536          // floats per smem row (= output row seg), stride = row

__global__ __launch_bounds__(THREADS, 4) void weave_kernel(
    const float4* __restrict__ in4,   // (32, 768, 768) pixels, 1 float4 each
    float4* __restrict__ out4)        // (32, 1536, 384) float4
{
    __shared__ float smem[8 * ROWLEN];   // 49152 B = 48 KB exactly

    const int bid = blockIdx.x;
    const int yb  = bid % YB;
    const int b   = bid / YB;
    const int tid = threadIdx.x;

    // ---- Load: 4 rows x 768 px = 3072 float4 ----
    const int in_base = (b * 768 + yb * 4) * 768;

    #pragma unroll
    for (int k = 0; k < 6; k++) {
        const int i  = tid + k * THREADS;      // 0..3071
        const int py = i & 3;
        const int px = (i >> 2) & 3;
        const int xb = i >> 4;                 // 0..191
        const int xl = (xb << 2) + px;         // pixel x

        const float4 v = __ldcs(&in4[in_base + py * 768 + xl]);

        const int f   = px + ((px & 2) << 1);  // {0,1,6,7}
        const int c40 = ((xb << 1) ^ f);       // (2*xb + wi=0) ^ f
        const int a00 = px * ROWLEN + (c40 << 2) + py;          // hi=0, wi=0
        const int a01 = px * ROWLEN + ((c40 ^ 1) << 2) + py;    // hi=0, wi=1

        smem[a00]              = v.x;   // q=0: hi=0, wi=0
        smem[a01]              = v.y;   // q=1: hi=0, wi=1
        smem[a00 + 4 * ROWLEN] = v.z;   // q=2: hi=1, wi=0
        smem[a01 + 4 * ROWLEN] = v.w;   // q=3: hi=1, wi=1
    }

    __syncthreads();

    // ---- Store: 8 rows x 384 float4 = 3072 float4, fully coalesced ----
    const int out_base = (b * 1536 + yb * 8) * 384;

    #pragma unroll
    for (int k = 0; k < 6; k++) {
        const int j  = tid + k * THREADS;      // 0..3071
        const int r  = j / 384;                // 0..7 (warp never straddles rows)
        const int c4 = j - r * 384;            // 0..383
        const int rp = r & 3;                  // = px of this output row
        const int f  = rp + ((rp & 2) << 1);
        const float4 v = *reinterpret_cast<const float4*>(
            &smem[r * ROWLEN + ((c4 ^ f) << 2)]);
        __stcs(&out4[out_base + r * 384 + c4], v);
    }
}

extern "C" void kernel_launch(void* const* d_in, const int* in_sizes, int n_in,
                              void* d_out, int out_size) {
    const float4* in4 = (const float4*)d_in[0];
    float4* out4 = (float4*)d_out;
    weave_kernel<<<B_ * YB, THREADS>>>(in4, out4);
}